// round 11
// baseline (speedup 1.0000x reference)
#include <cuda_runtime.h>

// RankingLoss, N=16384.
// loss = (1/N) * sum_i [ cnt_i>0 ? (sum_{j: t_j<t_i} max(0, M - (p_i - p_j))) / cnt_i : 0 ]
//
// Sort by target (rank r): valid set {k<r}, cnt_r == r. Decompose {k<r}:
//  cross (target-chunks < cb): GLOBAL pred sort + per-cb cumulative tables
//    Mc[cb][j] / Ms[cb][j] = count/sum of prior-chunk preds among the j
//    globally smallest preds. Row r: one search m = #{p <= p_r - M}, then
//    cross = (cb*1024 - Mc[cb][m])*si + (Ms[cb][NN] - Ms[cb][m]).  Exact.
//  diag (own chunk): 32-elem subwarp sorted structs (register bitonic);
//    prior subwarps via 5-step closed-form searches (split over 4 blocks),
//    own subwarp via shfl loop.
// All reductions fixed-order / order-invariant => deterministic.

#define NN 16384
#define TB 2048
#define PB 4096
#define GK1 16
#define TPB 1024
#define NCH 16
#define NSPLIT 4
#define GK2 (NCH * NSPLIT)
#define MARGIN 0.1f
#define FULLMASK 0xffffffffu

__device__ int   g_tcnt[TB];          // zero at entry; re-zeroed in Ph2
__device__ int   g_tcur[TB];          // zero at entry; re-zeroed in Ph3
__device__ int   g_toff[TB + 1];
__device__ int   g_pcnt[PB];
__device__ int   g_pcur[PB];
__device__ int   g_poff[PB + 1];
__device__ unsigned long long g_tkey[NN];   // (target_bits<<32) | idx
__device__ float g_tval[NN];                // pred carried with target key
__device__ unsigned long long g_pkey[NN];   // (mapped pred bits<<32) | idx
__device__ float g_pval[NN];
__device__ int   g_trank[NN];               // target rank of original idx
__device__ float g_ps[NN];                  // preds in target order
__device__ __align__(16) float g_sortedp[NN];  // preds ascending
__device__ int   g_porig[NN];               // original idx of pred-rank j
__device__ float g_Mc[NCH][NN + 1];         // cumulative count tables
__device__ float g_Ms[NCH][NN + 1];         // cumulative sum tables
__device__ float g_fence[1024];             // sortedp[16k+15]
__device__ float g_ws[NN];                  // subwarp-sorted preds
__device__ float g_wp[NN];                  // subwarp exclusive prefix
__device__ float g_wtot[NCH * 32];          // subwarp totals
__device__ float g_acc0[NN];                // cross + own-sub + split-0 diag
__device__ float g_dacc[NSPLIT - 1][NN];    // split 1..3 diag partials
__device__ unsigned          g_bar_cnt = 0;
__device__ volatile unsigned g_bar_gen = 0;
__device__ unsigned          g_done = 0;

__device__ __forceinline__ void grid_bar() {
    __syncthreads();
    if (threadIdx.x == 0) {
        unsigned my = g_bar_gen;
        __threadfence();
        if (atomicAdd(&g_bar_cnt, 1) == (unsigned)(GK1 - 1)) {
            g_bar_cnt = 0;
            __threadfence();
            g_bar_gen = my + 1;
        } else {
            while (g_bar_gen == my) { }
        }
        __threadfence();
    }
    __syncthreads();
}

__device__ __forceinline__ int tb_of(float t) {
    int b = (int)(t * (float)TB);
    return b < 0 ? 0 : (b > TB - 1 ? TB - 1 : b);
}
__device__ __forceinline__ int pb_of(float p) {
    int b = (int)((p + 8.0f) * ((float)PB / 16.0f));
    return b < 0 ? 0 : (b > PB - 1 ? PB - 1 : b);
}

// Block-wide inclusive scan of one float per thread (1024 threads).
// After return (last op is syncthreads), sm[31] holds the block total.
__device__ __forceinline__ float blk_scan(float v, float* sm, int lane, int w) {
    float x = v;
#pragma unroll
    for (int d = 1; d < 32; d <<= 1) {
        float o = __shfl_up_sync(FULLMASK, x, d);
        if (lane >= d) x += o;
    }
    if (lane == 31) sm[w] = x;
    __syncthreads();
    if (w == 0) {
        float y = sm[lane];
#pragma unroll
        for (int d = 1; d < 32; d <<= 1) {
            float o = __shfl_up_sync(FULLMASK, y, d);
            if (lane >= d) y += o;
        }
        sm[lane] = y;
    }
    __syncthreads();
    float off = (w > 0) ? sm[w - 1] : 0.0f;
    return off + x;
}

// ==================== K1: sorts + tables (16 x 1024) ====================
__global__ void __launch_bounds__(TPB)
build_kernel(const float* __restrict__ pred, const float* __restrict__ target) {
    __shared__ float sW[32];
    __shared__ float sS[32];

    const int t    = threadIdx.x;
    const int b    = blockIdx.x;
    const int gtid = b * TPB + t;           // exactly covers [0, NN)
    const int lane = t & 31;
    const int w    = t >> 5;

    const float tv = target[gtid];
    const float pv = pred[gtid];

    // ---- Ph0: both histograms ----
    atomicAdd(&g_tcnt[tb_of(tv)], 1);
    atomicAdd(&g_pcnt[pb_of(pv)], 1);
    grid_bar();

    // ---- Ph1: block 0 scans target counts, block 1 scans pred counts ----
    if (b == 0) {
        int* sm = (int*)sW;
        const int base = t * 2;
        int c0 = g_tcnt[base], c1 = g_tcnt[base + 1];
        int s = c0 + c1;
        int x = s;
#pragma unroll
        for (int d = 1; d < 32; d <<= 1) {
            int o = __shfl_up_sync(FULLMASK, x, d);
            if (lane >= d) x += o;
        }
        if (lane == 31) sm[w] = x;
        __syncthreads();
        if (w == 0) {
            int y = sm[lane];
#pragma unroll
            for (int d = 1; d < 32; d <<= 1) {
                int o = __shfl_up_sync(FULLMASK, y, d);
                if (lane >= d) y += o;
            }
            sm[lane] = y;
        }
        __syncthreads();
        int run = ((w > 0) ? sm[w - 1] : 0) + x - s;
        g_toff[base] = run;
        g_toff[base + 1] = run + c0;
        if (t == TPB - 1) g_toff[TB] = run + s;
    } else if (b == 1) {
        int* sm = (int*)sW;
        const int base = t * 4;
        int loc[4];
        int s = 0;
#pragma unroll
        for (int k = 0; k < 4; k++) { loc[k] = g_pcnt[base + k]; s += loc[k]; }
        int x = s;
#pragma unroll
        for (int d = 1; d < 32; d <<= 1) {
            int o = __shfl_up_sync(FULLMASK, x, d);
            if (lane >= d) x += o;
        }
        if (lane == 31) sm[w] = x;
        __syncthreads();
        if (w == 0) {
            int y = sm[lane];
#pragma unroll
            for (int d = 1; d < 32; d <<= 1) {
                int o = __shfl_up_sync(FULLMASK, y, d);
                if (lane >= d) y += o;
            }
            sm[lane] = y;
        }
        __syncthreads();
        int run = ((w > 0) ? sm[w - 1] : 0) + x - s;
#pragma unroll
        for (int k = 0; k < 4; k++) { g_poff[base + k] = run; run += loc[k]; }
        if (t == TPB - 1) g_poff[PB] = run;
    }
    grid_bar();

    // ---- Ph2: both scatters; re-zero counts ----
    {
        int bk = tb_of(tv);
        int pos = g_toff[bk] + atomicAdd(&g_tcur[bk], 1);
        // targets in [0,1): sign bit 0 -> raw bits are order-preserving
        g_tkey[pos] = ((unsigned long long)__float_as_uint(tv) << 32) | (unsigned)gtid;
        g_tval[pos] = pv;

        unsigned pbits = __float_as_uint(pv);
        unsigned mapped = pbits ^ ((pbits >> 31) ? 0xFFFFFFFFu : 0x80000000u);
        int pk = pb_of(pv);
        int pp = g_poff[pk] + atomicAdd(&g_pcur[pk], 1);
        g_pkey[pp] = ((unsigned long long)mapped << 32) | (unsigned)gtid;
        g_pval[pp] = pv;

        if (gtid < TB) g_tcnt[gtid] = 0;
        if (gtid < PB) g_pcnt[gtid] = 0;
    }
    grid_bar();

    // ---- Ph3: exact ranks (order-invariant => deterministic); zero cursors ----
    {
        unsigned long long key = g_tkey[gtid];
        float tvv = __uint_as_float((unsigned)(key >> 32));
        int bk = tb_of(tvv);
        int lo = g_toff[bk], hi = g_toff[bk + 1];
        int r = lo;
        for (int m = lo; m < hi; m++) r += (g_tkey[m] < key) ? 1 : 0;
        g_ps[r] = g_tval[gtid];
        g_trank[(int)(key & 0xffffffffu)] = r;

        unsigned long long pkk = g_pkey[gtid];
        float pvv = g_pval[gtid];
        int pbk = pb_of(pvv);
        lo = g_poff[pbk]; hi = g_poff[pbk + 1];
        int j = lo;
        for (int m = lo; m < hi; m++) j += (g_pkey[m] < pkk) ? 1 : 0;
        g_sortedp[j] = pvv;
        g_porig[j] = (int)(pkk & 0xffffffffu);

        if (gtid < TB) g_tcur[gtid] = 0;
        if (gtid < PB) g_pcur[gtid] = 0;
    }
    grid_bar();

    // ---- Ph4a: subwarp sorted structs (block b = chunk b), zero barriers ----
    {
        float p = g_ps[b * TPB + t];
#pragma unroll
        for (int k = 2; k <= 32; k <<= 1) {
#pragma unroll
            for (int j = k >> 1; j > 0; j >>= 1) {
                float o = __shfl_xor_sync(FULLMASK, p, j);
                bool up  = ((lane & k) == 0);
                bool low = ((lane & j) == 0);
                float mn = fminf(p, o), mx = fmaxf(p, o);
                p = (up == low) ? mn : mx;
            }
        }
        float v = p;
#pragma unroll
        for (int d = 1; d < 32; d <<= 1) {
            float o = __shfl_up_sync(FULLMASK, v, d);
            if (lane >= d) v += o;
        }
        float wt = __shfl_sync(FULLMASK, v, 31);
        g_ws[b * TPB + t] = p;
        g_wp[b * TPB + t] = v - p;
        if (lane == 31) g_wtot[b * 32 + w] = wt;
    }

    // ---- Ph4b: block 0 builds fences; blocks 1..15 build M tables ----
    if (b == 0) {
        g_fence[t] = g_sortedp[t * 16 + 15];
    } else {
        const int cb = b;
        if (t == 0) { g_Mc[cb][0] = 0.0f; g_Ms[cb][0] = 0.0f; }
        float cc = 0.0f, cs = 0.0f;
        for (int rd = 0; rd < NN / TPB; rd++) {
            int j = rd * TPB + t;
            bool ind = (g_trank[g_porig[j]] >> 10) < cb;
            float vc = ind ? 1.0f : 0.0f;
            float vs = ind ? g_sortedp[j] : 0.0f;
            float ic = blk_scan(vc, sW, lane, w);
            float tot_c = sW[31];
            float is = blk_scan(vs, sS, lane, w);
            float tot_s = sS[31];
            g_Mc[cb][j + 1] = cc + ic;
            g_Ms[cb][j + 1] = cs + is;
            cc += tot_c;
            cs += tot_s;
        }
    }
}

// ==================== K2: per-row loss (64 x 1024, no barriers) ====================
__global__ void __launch_bounds__(TPB)
row_kernel(float* __restrict__ out) {
    __shared__ float sws[1024];
    __shared__ float swp[1024];
    __shared__ float sfe[1024];
    __shared__ float swt[32];
    __shared__ unsigned s_last;

    const int t    = threadIdx.x;
    const int lane = t & 31;
    const int w    = t >> 5;
    const int cb   = blockIdx.x & (NCH - 1);
    const int s    = blockIdx.x >> 4;

    sws[t] = g_ws[cb * TPB + t];
    swp[t] = g_wp[cb * TPB + t];
    if (t < 32) swt[t] = g_wtot[cb * 32 + t];
    if (s == 0) sfe[t] = g_fence[t];
    __syncthreads();

    const int r = cb * TPB + t;
    const float pown = g_ps[r];
    const float si   = MARGIN - pown;
    const float key  = pown - MARGIN;      // == -si

    // Prior-subwarp closed forms for this split (independent searches -> MLP).
    float acc = 0.0f;
    {
        const int lo = s * 8;
        const int hi = (w < (s + 1) * 8) ? w : (s + 1) * 8;
        for (int w2 = lo; w2 < hi; w2++) {
            const int bs = w2 * 32;
            int m = 0;
#pragma unroll
            for (int step = 32; step > 0; step >>= 1)
                if (m + step <= 32 && sws[bs + m + step - 1] <= key) m += step;
            float Pm = (m < 32) ? swp[bs + m] : swt[w2];
            acc += (float)(32 - m) * si + (swt[w2] - Pm);
        }
    }

    if (s == 0) {
        // Global search: m = #{sortedp <= key} via fences + one 16-seg scan.
        int nf = 0;
#pragma unroll
        for (int step = 1024; step > 0; step >>= 1)
            if (nf + step <= 1024 && sfe[nf + step - 1] <= key) nf += step;
        int m;
        if (nf == 1024) {
            m = NN;
        } else {
            const float4* p4 = (const float4*)(g_sortedp + nf * 16);
            float4 a = p4[0], bq = p4[1], c = p4[2], d = p4[3];
            int cnt = (a.x <= key) + (a.y <= key) + (a.z <= key) + (a.w <= key)
                    + (bq.x <= key) + (bq.y <= key) + (bq.z <= key) + (bq.w <= key)
                    + (c.x <= key) + (c.y <= key) + (c.z <= key) + (c.w <= key)
                    + (d.x <= key) + (d.y <= key) + (d.z <= key) + (d.w <= key);
            m = nf * 16 + cnt;
        }

        float cross = 0.0f;
        if (cb > 0) {
            float Cm = g_Mc[cb][m];
            float Sm = g_Ms[cb][m];
            float Ct = (float)(cb * TPB);
            float St = g_Ms[cb][NN];
            cross = (Ct - Cm) * si + (St - Sm);
        }

        float own = 0.0f;
#pragma unroll
        for (int k2 = 0; k2 < 32; k2++) {
            float o = __shfl_sync(FULLMASK, pown, k2);
            if (k2 < lane) own += fmaxf(si + o, 0.0f);
        }
        g_acc0[r] = cross + own + acc;
    } else {
        g_dacc[s - 1][r] = acc;
    }

    // Last-arriving block does the final reduce (fixed order => deterministic).
    __threadfence();
    __syncthreads();
    if (t == 0) s_last = (atomicAdd(&g_done, 1) == (unsigned)(GK2 - 1));
    __syncthreads();
    if (!s_last) return;
    if (t == 0) g_done = 0;                // reset for next graph replay
    __threadfence();

    float local = 0.0f;
    for (int rr = t; rr < NN; rr += TPB) {
        if (rr == 0) continue;
        float S = g_acc0[rr];
#pragma unroll
        for (int q = 0; q < NSPLIT - 1; q++) S += g_dacc[q][rr];
        local += S / (float)rr;            // cnt_r == r
    }
    __syncthreads();
    sws[t] = local;
    __syncthreads();
#pragma unroll
    for (int off = TPB / 2; off > 0; off >>= 1) {
        if (t < off) sws[t] += sws[t + off];
        __syncthreads();
    }
    if (t == 0) out[0] = sws[0] / (float)NN;
}

extern "C" void kernel_launch(void* const* d_in, const int* in_sizes, int n_in,
                              void* d_out, int out_size) {
    const float* pred   = (const float*)d_in[0];
    const float* target = (const float*)d_in[1];
    float* out = (float*)d_out;
    (void)in_sizes; (void)n_in; (void)out_size;

    build_kernel<<<GK1, TPB>>>(pred, target);
    row_kernel<<<GK2, TPB>>>(out);
}

// round 12
// speedup vs baseline: 1.2690x; 1.2690x over previous
#include <cuda_runtime.h>

// RankingLoss, N=16384.
// loss = (1/N) * sum_i [ cnt_i>0 ? (sum_{j: t_j<t_i} max(0, M - (p_i - p_j))) / cnt_i : 0 ]
//
// Rank by target (rank r): valid set {k<r}, cnt_r == r. Decompose {k<r}:
//  cross (target-chunks < cb): global pred sort + per-cb sliced cumulative
//    tables; row r: one search m = #{p <= p_r - M}, two lookups. Tie-exact.
//  diag (own chunk): direct hinge evaluation, chunk split into k-quarters.
// K1: dual bucket-rank sorts (16 blocks, 3 grid bars).
// K2: 240 table blocks (one scan each) + 64 diag blocks + 1 fence block.
// K3: 16 cross blocks; last-arriving block does the final reduce.
// All reductions fixed-order / order-invariant => deterministic.

#define NN 16384
#define TB 4096
#define PB 4096
#define GK1 16
#define TPB 1024
#define NCH 16
#define MARGIN 0.1f
#define FULLMASK 0xffffffffu

__device__ int   g_tcnt[TB];          // zero at entry; re-zeroed in Ph2
__device__ int   g_tcur[TB];          // zero at entry; re-zeroed in Ph3
__device__ int   g_toff[TB + 1];
__device__ int   g_pcnt[PB];
__device__ int   g_pcur[PB];
__device__ int   g_poff[PB + 1];
__device__ unsigned long long g_tkey[NN];     // (target_bits<<32) | idx
__device__ float g_tval[NN];
__device__ unsigned long long g_pkey[NN];     // (mapped pred bits<<32) | idx
__device__ float g_pval[NN];
__device__ int   g_trank[NN];                 // target rank of original idx
__device__ float g_ps[NN];                    // preds in target order
__device__ __align__(16) float g_sortedp[NN]; // preds ascending
__device__ int   g_porig[NN];                 // original idx of pred-rank j
__device__ float g_Lc[NCH][NN];               // sliced inclusive count prefix
__device__ float g_Ls[NCH][NN];               // sliced inclusive sum prefix
__device__ float g_Tc[NCH][NCH];              // slice totals (count)
__device__ float g_Ts[NCH][NCH];              // slice totals (sum)
__device__ float g_fence[1024];               // sortedp[16k+15]
__device__ float g_cross[NN];
__device__ float g_dacc[4][NN];               // diag quarter partials
__device__ unsigned          g_bar_cnt = 0;
__device__ volatile unsigned g_bar_gen = 0;
__device__ unsigned          g_done = 0;

__device__ __forceinline__ void grid_bar() {
    __syncthreads();
    if (threadIdx.x == 0) {
        unsigned my = g_bar_gen;
        __threadfence();
        if (atomicAdd(&g_bar_cnt, 1) == (unsigned)(GK1 - 1)) {
            g_bar_cnt = 0;
            __threadfence();
            g_bar_gen = my + 1;
        } else {
            while (g_bar_gen == my) { }
        }
        __threadfence();
    }
    __syncthreads();
}

__device__ __forceinline__ int tb_of(float t) {
    int b = (int)(t * (float)TB);
    return b < 0 ? 0 : (b > TB - 1 ? TB - 1 : b);
}
__device__ __forceinline__ int pb_of(float p) {
    int b = (int)((p + 8.0f) * ((float)PB / 16.0f));
    return b < 0 ? 0 : (b > PB - 1 ? PB - 1 : b);
}

// Block-wide inclusive scan (1024 threads, one float each). sm has 32 slots.
// Caller may read sm only before issuing another scan on the same buffer.
__device__ __forceinline__ float blk_scan(float v, float* sm, int lane, int w) {
    float x = v;
#pragma unroll
    for (int d = 1; d < 32; d <<= 1) {
        float o = __shfl_up_sync(FULLMASK, x, d);
        if (lane >= d) x += o;
    }
    if (lane == 31) sm[w] = x;
    __syncthreads();
    if (w == 0) {
        float y = sm[lane];
#pragma unroll
        for (int d = 1; d < 32; d <<= 1) {
            float o = __shfl_up_sync(FULLMASK, y, d);
            if (lane >= d) y += o;
        }
        sm[lane] = y;
    }
    __syncthreads();
    float off = (w > 0) ? sm[w - 1] : 0.0f;
    return off + x;
}

// ==================== K1: dual bucket-rank sorts (16 x 1024) ====================
__global__ void __launch_bounds__(TPB)
sort_kernel(const float* __restrict__ pred, const float* __restrict__ target) {
    __shared__ int sW[32];

    const int t    = threadIdx.x;
    const int b    = blockIdx.x;
    const int gtid = b * TPB + t;          // exactly covers [0, NN)
    const int lane = t & 31;
    const int w    = t >> 5;

    const float tv = target[gtid];
    const float pv = pred[gtid];

    // Ph0: both histograms (counts zero at entry).
    atomicAdd(&g_tcnt[tb_of(tv)], 1);
    atomicAdd(&g_pcnt[pb_of(pv)], 1);
    grid_bar();

    // Ph1: block 0 -> target offsets, block 1 -> pred offsets (4096 each).
    if (b < 2) {
        const int* cnt = (b == 0) ? g_tcnt : g_pcnt;
        int*       off = (b == 0) ? g_toff : g_poff;
        const int base = t * 4;
        int loc[4];
        int s = 0;
#pragma unroll
        for (int k = 0; k < 4; k++) { loc[k] = cnt[base + k]; s += loc[k]; }
        int x = s;
#pragma unroll
        for (int d = 1; d < 32; d <<= 1) {
            int o = __shfl_up_sync(FULLMASK, x, d);
            if (lane >= d) x += o;
        }
        if (lane == 31) sW[w] = x;
        __syncthreads();
        if (w == 0) {
            int y = sW[lane];
#pragma unroll
            for (int d = 1; d < 32; d <<= 1) {
                int o = __shfl_up_sync(FULLMASK, y, d);
                if (lane >= d) y += o;
            }
            sW[lane] = y;
        }
        __syncthreads();
        int run = ((w > 0) ? sW[w - 1] : 0) + x - s;
#pragma unroll
        for (int k = 0; k < 4; k++) { off[base + k] = run; run += loc[k]; }
        if (t == TPB - 1) off[(b == 0) ? TB : PB] = run;
    }
    grid_bar();

    // Ph2: both scatters; re-zero counts.
    {
        int bk = tb_of(tv);
        int pos = g_toff[bk] + atomicAdd(&g_tcur[bk], 1);
        // targets in [0,1): sign bit 0 -> raw bits order-preserving
        g_tkey[pos] = ((unsigned long long)__float_as_uint(tv) << 32) | (unsigned)gtid;
        g_tval[pos] = pv;

        unsigned pbits = __float_as_uint(pv);
        unsigned mapped = pbits ^ ((pbits >> 31) ? 0xFFFFFFFFu : 0x80000000u);
        int pk = pb_of(pv);
        int pp = g_poff[pk] + atomicAdd(&g_pcur[pk], 1);
        g_pkey[pp] = ((unsigned long long)mapped << 32) | (unsigned)gtid;
        g_pval[pp] = pv;

        if (gtid < TB) g_tcnt[gtid] = 0;
        if (gtid < PB) g_pcnt[gtid] = 0;
    }
    grid_bar();

    // Ph3: exact in-bucket ranks (order-invariant => deterministic).
    {
        unsigned long long key = g_tkey[gtid];
        float tvv = __uint_as_float((unsigned)(key >> 32));
        int bk = tb_of(tvv);
        int lo = g_toff[bk], hi = g_toff[bk + 1];
        int r = lo;
        for (int m = lo; m < hi; m++) r += (g_tkey[m] < key) ? 1 : 0;
        g_ps[r] = g_tval[gtid];
        g_trank[(int)(key & 0xffffffffu)] = r;

        unsigned long long pkk = g_pkey[gtid];
        float pvv = g_pval[gtid];
        int pbk = pb_of(pvv);
        lo = g_poff[pbk]; hi = g_poff[pbk + 1];
        int j = lo;
        for (int m = lo; m < hi; m++) j += (g_pkey[m] < pkk) ? 1 : 0;
        g_sortedp[j] = pvv;
        g_porig[j] = (int)(pkk & 0xffffffffu);

        if (gtid < TB) g_tcur[gtid] = 0;
        if (gtid < PB) g_pcur[gtid] = 0;
    }
}

// ==================== K2: tables + diag + fence (305 blocks) ====================
__global__ void __launch_bounds__(TPB)
build_kernel() {
    const int id = blockIdx.x;
    const int t  = threadIdx.x;

    if (id < 240) {
        // Table block: cb in 1..15, j-slice jb in 0..15. One scan, no carry.
        __shared__ float sW[32];
        __shared__ float sS[32];
        const int cb = 1 + id / 16;
        const int jb = id % 16;
        const int lane = t & 31;
        const int w = t >> 5;
        const int j = jb * 1024 + t;

        int idx = g_porig[j];
        int rk  = g_trank[idx];
        bool ind = (rk >> 10) < cb;
        float vc = ind ? 1.0f : 0.0f;
        float vs = ind ? g_sortedp[j] : 0.0f;
        float ic = blk_scan(vc, sW, lane, w);
        float is = blk_scan(vs, sS, lane, w);
        g_Lc[cb][j] = ic;
        g_Ls[cb][j] = is;
        if (t == TPB - 1) { g_Tc[cb][jb] = ic; g_Ts[cb][jb] = is; }
    } else if (id < 304) {
        // Diagonal block: chunk c, k-quarter q. Direct hinge eval (exact).
        __shared__ float sh[256];
        const int d = id - 240;
        const int c = d >> 2;
        const int q = d & 3;
        if (t < 256) sh[t] = g_ps[c * 1024 + q * 256 + t];
        __syncthreads();

        const int nrows = 1024 - q * 256;
        if (t < nrows) {
            const int rl = q * 256 + t;
            const int r = c * 1024 + rl;
            const float si = MARGIN - g_ps[r];
            const int width = (t < 256) ? t : 256;
            const float4* s4 = (const float4*)sh;
            float a0 = 0.f, a1 = 0.f, a2 = 0.f, a3 = 0.f;
            int k = 0;
            for (; k + 4 <= width; k += 4) {
                float4 v = s4[k >> 2];
                a0 += fmaxf(si + v.x, 0.f);
                a1 += fmaxf(si + v.y, 0.f);
                a2 += fmaxf(si + v.z, 0.f);
                a3 += fmaxf(si + v.w, 0.f);
            }
            float acc = (a0 + a1) + (a2 + a3);
            for (; k < width; k++) acc += fmaxf(si + sh[k], 0.f);
            g_dacc[q][r] = acc;
        }
    } else {
        // Fence block.
        g_fence[t] = g_sortedp[t * 16 + 15];
    }
}

// ==================== K3: cross + last-arrival reduce (16 blocks) ====================
__global__ void __launch_bounds__(TPB)
cross_kernel(float* __restrict__ out) {
    __shared__ float sfe[1024];
    __shared__ float sc[17];
    __shared__ float ss[17];
    __shared__ unsigned s_last;

    const int t  = threadIdx.x;
    const int cb = blockIdx.x;

    if (cb == 0) {
        g_cross[t] = 0.0f;               // chunk 0 has no cross term
    } else {
        sfe[t] = g_fence[t];
        if (t == 0) {
            float rc = 0.0f, rs = 0.0f;
#pragma unroll
            for (int jb = 0; jb < 16; jb++) {
                sc[jb] = rc; ss[jb] = rs;
                rc += g_Tc[cb][jb]; rs += g_Ts[cb][jb];
            }
            sc[16] = rc; ss[16] = rs;
        }
        __syncthreads();

        const int r = cb * 1024 + t;
        const float pown = g_ps[r];
        const float si = MARGIN - pown;
        const float key = pown - MARGIN;

        // m = #{sortedp <= key}: fence search + one 16-wide segment.
        int nf = 0;
#pragma unroll
        for (int s2 = 512; s2 > 0; s2 >>= 1)
            if (sfe[nf + s2 - 1] <= key) nf += s2;
        if (nf == 1023 && sfe[1023] <= key) nf = 1024;
        int m;
        if (nf == 1024) {
            m = NN;
        } else {
            const float4* p4 = (const float4*)(g_sortedp + nf * 16);
            float4 a = p4[0], bq = p4[1], c4 = p4[2], d4 = p4[3];
            int cnt = (a.x <= key) + (a.y <= key) + (a.z <= key) + (a.w <= key)
                    + (bq.x <= key) + (bq.y <= key) + (bq.z <= key) + (bq.w <= key)
                    + (c4.x <= key) + (c4.y <= key) + (c4.z <= key) + (c4.w <= key)
                    + (d4.x <= key) + (d4.y <= key) + (d4.z <= key) + (d4.w <= key);
            m = nf * 16 + cnt;
        }

        // Hc/Hs = count/sum of prior-chunk preds among the m smallest.
        const int jb2 = m >> 10;
        const int lm = m & 1023;
        float Hc = sc[jb2], Hs = ss[jb2];
        if (lm) { Hc += g_Lc[cb][m - 1]; Hs += g_Ls[cb][m - 1]; }

        g_cross[r] = ((float)(cb * 1024) - Hc) * si + (ss[16] - Hs);
    }

    // Last-arriving block does the final reduce (fixed order => deterministic).
    __threadfence();
    __syncthreads();
    if (t == 0) s_last = (atomicAdd(&g_done, 1) == (unsigned)(NCH - 1));
    __syncthreads();
    if (!s_last) return;
    if (t == 0) g_done = 0;              // reset for next graph replay
    __threadfence();

    float local = 0.0f;
    for (int rr = t; rr < NN; rr += TPB) {
        if (rr == 0) continue;
        const int rl = rr & 1023;
        float S = g_cross[rr];
        const int qmax = rl >> 8;
        for (int q = 0; q <= qmax; q++) S += g_dacc[q][rr];
        local += S / (float)rr;          // cnt_r == r
    }
    __syncthreads();
    sfe[t] = local;
    __syncthreads();
#pragma unroll
    for (int off = TPB / 2; off > 0; off >>= 1) {
        if (t < off) sfe[t] += sfe[t + off];
        __syncthreads();
    }
    if (t == 0) out[0] = sfe[0] / (float)NN;
}

extern "C" void kernel_launch(void* const* d_in, const int* in_sizes, int n_in,
                              void* d_out, int out_size) {
    const float* pred   = (const float*)d_in[0];
    const float* target = (const float*)d_in[1];
    float* out = (float*)d_out;
    (void)in_sizes; (void)n_in; (void)out_size;

    sort_kernel <<<GK1, TPB>>>(pred, target);
    build_kernel<<<305, TPB>>>();
    cross_kernel<<<NCH, TPB>>>(out);
}